// round 4
// baseline (speedup 1.0000x reference)
#include <cuda_runtime.h>

// NNSystem_mech: tiny neuro-endocrine ODE RHS. Single-warp, minimal-launch-cost.
// Input order (metadata):
// 0 t, 1 y, 2 aiw, 3 aib, 4 apw1, 5 apb1, 6 apw2, 7 apb2,
// 8 anw1, 9 anb1, 10 anw2, 11 anb2, 12 arw, 13 arb,
// 14 ciw, 15 cib, 16 cpw1, 17 cpb1, 18 cpw2, 19 cpb2,
// 20 cnw1, 21 cnb1, 22 cnw2, 23 cnb2, 24 crw, 25 crb, 26 K_i, 27 n_hill
//
// Strategy: the kernel is ~300 cycles of real work inside a multi-microsecond
// launch envelope (R1 64thr/smem/powf and R2 32thr/shfl/MUFU both timed
// 6.879999us exactly). This round minimizes launch-side cost: 2-pointer param
// block (instead of 28), 32 regs, one warp, tiny SASS body.

__device__ __forceinline__ float softplus_fast(float x) {
    float e = __expf(-fabsf(x));
    return fmaxf(x, 0.0f) + __logf(1.0f + e);
}

__device__ __forceinline__ float pow_pos(float b, float n) {
    return exp2f(n * __log2f(b));   // base strictly positive here
}

__global__ __launch_bounds__(32, 1)
void nnsys_kernel(const float* const* __restrict__ din, float* __restrict__ out) {
    const int lane = threadIdx.x;          // 0..31
    const int seg  = lane >> 3;            // 0=a_pos 1=a_neg 2=c_pos 3=c_neg
    const int u0   = lane & 7;             // hidden unit (8,9 handled by u0<2)

    // pointer table: 1 cache line, uniform across lanes
    const float* y  = din[1];
    const float y0 = __ldg(&y[0]);
    const float y1 = __ldg(&y[1]);

    // group -> input-buffer indices: {iw_buf, w1, b1, w2, b2}
    // seg0: aiw[0], 4,5,6,7   seg1: aiw[1], 8,9,10,11
    // seg2: ciw[0], 16..19    seg3: ciw[1], 20..23
    const int base   = (seg < 2) ? 4 + 4 * seg : 8 + 4 * seg;   // 4,8,16,20
    const int iwbuf  = (seg < 2) ? 2 : 14;                      // aiw/ciw
    const int sel    = seg & 1;                                 // component
    const float yin  = (seg < 2) ? y0 : y1;

    const float iw = __ldg(&din[iwbuf][sel]);
    const float ib = __ldg(&din[iwbuf + 1][sel]);
    const float* w1p = din[base];
    const float* b1p = din[base + 1];
    const float* w2p = din[base + 2];
    const float b2   = __ldg(&din[base + 3][0]);

    // issue all hidden-unit loads up front (independent of front softplus)
    const float w1a = __ldg(&w1p[u0]), b1a = __ldg(&b1p[u0]), w2a = __ldg(&w2p[u0]);
    const bool second = (u0 < 2);
    float w1b = 0.f, b1b = 0.f, w2b = 0.f;
    if (second) { w1b = __ldg(&w1p[8 + u0]); b1b = __ldg(&b1p[8 + u0]); w2b = __ldg(&w2p[8 + u0]); }

    // tail params (only lane 0 consumes; loads overlap the MUFU chain)
    const float arw0 = __ldg(&din[12][0]), arw1 = __ldg(&din[12][1]), arb = __ldg(&din[13][0]);
    const float crw0 = __ldg(&din[24][0]), crw1 = __ldg(&din[24][1]), crb = __ldg(&din[25][0]);
    const float Ki   = __ldg(&din[26][0]), nh  = __ldg(&din[27][0]);

    // ---- compute ----
    const float x = softplus_fast(fmaf(iw, yin, ib));

    float local = w2a * softplus_fast(fmaf(w1a, x, b1a));
    if (second) local = fmaf(w2b, softplus_fast(fmaf(w1b, x, b1b)), local);
    if (u0 == 0) local += b2;

    // width-8 butterfly reduce, then pull the 4 segment sums into lane 0
    local += __shfl_xor_sync(0xffffffffu, local, 1, 8);
    local += __shfl_xor_sync(0xffffffffu, local, 2, 8);
    local += __shfl_xor_sync(0xffffffffu, local, 4, 8);

    const float a_pos = __shfl_sync(0xffffffffu, local, 0);
    const float a_neg = __shfl_sync(0xffffffffu, local, 8);
    const float c_pos = __shfl_sync(0xffffffffu, local, 16);
    const float c_neg = __shfl_sync(0xffffffffu, local, 24);

    if (lane == 0) {
        const float Kn   = pow_pos(Ki, nh);
        const float hill = Kn / (Kn + pow_pos(y1, nh));

        const float av0 = softplus_fast(hill * a_pos);
        const float av1 = softplus_fast(a_neg);
        const float cv0 = softplus_fast(y0 * c_pos);
        const float cv1 = softplus_fast(c_neg);

        float2 r;
        r.x = fmaf(arw0, av0, fmaf(arw1, av1, arb));
        r.y = fmaf(crw0, cv0, fmaf(crw1, cv1, crb));
        *reinterpret_cast<float2*>(out) = r;
    }
}

extern "C" void kernel_launch(void* const* d_in, const int* in_sizes, int n_in,
                              void* d_out, int out_size) {
    (void)in_sizes; (void)n_in; (void)out_size;
    nnsys_kernel<<<1, 32>>>((const float* const*)d_in, (float*)d_out);
}

// round 5
// speedup vs baseline: 1.1495x; 1.1495x over previous
#include <cuda_runtime.h>

// NNSystem_mech: tiny neuro-endocrine ODE RHS. Single warp, params in constant
// bank (R3 showed device-side pointer indirection costs a dependent L2 wave).
// Hill term computed off-critical-path; tail split across lanes 0 and 16.

struct Params {
    const float* y;
    const float* aiw; const float* aib;
    const float* apw1; const float* apb1; const float* apw2; const float* apb2;
    const float* anw1; const float* anb1; const float* anw2; const float* anb2;
    const float* arw; const float* arb;
    const float* ciw; const float* cib;
    const float* cpw1; const float* cpb1; const float* cpw2; const float* cpb2;
    const float* cnw1; const float* cnb1; const float* cnw2; const float* cnb2;
    const float* crw; const float* crb;
    const float* K_i; const float* n_hill;
};

__device__ __forceinline__ float softplus_fast(float x) {
    float e = __expf(-fabsf(x));
    return fmaxf(x, 0.0f) + __logf(1.0f + e);
}

__device__ __forceinline__ float pow_pos(float b, float n) {
    return exp2f(n * __log2f(b));   // base strictly positive here
}

__global__ __launch_bounds__(32, 1)
void nnsys_kernel(Params p, float* __restrict__ out) {
    const int lane = threadIdx.x;          // 0..31
    const int seg  = lane >> 3;            // 0=a_pos 1=a_neg 2=c_pos 3=c_neg
    const int u0   = lane & 7;             // hidden unit (units 8,9 on u0<2)

    // ---- issue all independent loads up front ----
    const float y0 = p.y[0];
    const float y1 = p.y[1];
    const float Ki = p.K_i[0], nh = p.n_hill[0];

    float iw, ib, yin, b2;
    const float *w1p, *b1p, *w2p;
    if (seg == 0)      { iw = p.aiw[0]; ib = p.aib[0]; yin = y0; b2 = p.apb2[0];
                         w1p = p.apw1; b1p = p.apb1; w2p = p.apw2; }
    else if (seg == 1) { iw = p.aiw[1]; ib = p.aib[1]; yin = y0; b2 = p.anb2[0];
                         w1p = p.anw1; b1p = p.anb1; w2p = p.anw2; }
    else if (seg == 2) { iw = p.ciw[0]; ib = p.cib[0]; yin = y1; b2 = p.cpb2[0];
                         w1p = p.cpw1; b1p = p.cpb1; w2p = p.cpw2; }
    else               { iw = p.ciw[1]; ib = p.cib[1]; yin = y1; b2 = p.cnb2[0];
                         w1p = p.cnw1; b1p = p.cnb1; w2p = p.cnw2; }

    const float w1a = w1p[u0], b1a = b1p[u0], w2a = w2p[u0];
    const bool second = (u0 < 2);
    float w1b = 0.f, b1b = 0.f, w2b = 0.f;
    if (second) { w1b = w1p[8 + u0]; b1b = b1p[8 + u0]; w2b = w2p[8 + u0]; }

    // tail readout params: lane 0 -> acth (arw/arb), lane 16 -> cort (crw/crb)
    float rw0, rw1, rb;
    if (lane < 16) { rw0 = p.arw[0]; rw1 = p.arw[1]; rb = p.arb[0]; }
    else           { rw0 = p.crw[0]; rw1 = p.crw[1]; rb = p.crb[0]; }

    // ---- Hill term: independent of MLP results; overlaps the MLP chain ----
    const float Kn   = pow_pos(Ki, nh);
    const float hill = Kn / (Kn + pow_pos(y1, nh));

    // ---- MLP chain ----
    const float x = softplus_fast(fmaf(iw, yin, ib));

    float local = w2a * softplus_fast(fmaf(w1a, x, b1a));
    if (second) local = fmaf(w2b, softplus_fast(fmaf(w1b, x, b1b)), local);
    if (u0 == 0) local += b2;

    // width-8 butterfly: every lane in a segment holds its segment sum
    local += __shfl_xor_sync(0xffffffffu, local, 1, 8);
    local += __shfl_xor_sync(0xffffffffu, local, 2, 8);
    local += __shfl_xor_sync(0xffffffffu, local, 4, 8);

    // pair exchange: lane 0 gets a_neg (from lane 8), lane 16 gets c_neg (from 24)
    const float neg = __shfl_xor_sync(0xffffffffu, local, 8);

    if ((lane & 15) == 0) {               // lanes 0 and 16
        const float scale = (lane == 0) ? hill : y0;   // hill*a_pos  |  y0*c_pos
        const float v0 = softplus_fast(scale * local);
        const float v1 = softplus_fast(neg);
        out[lane >> 4] = fmaf(rw0, v0, fmaf(rw1, v1, rb));
    }
}

extern "C" void kernel_launch(void* const* d_in, const int* in_sizes, int n_in,
                              void* d_out, int out_size) {
    (void)in_sizes; (void)n_in; (void)out_size;
    Params p;
    p.y    = (const float*)d_in[1];
    p.aiw  = (const float*)d_in[2];  p.aib  = (const float*)d_in[3];
    p.apw1 = (const float*)d_in[4];  p.apb1 = (const float*)d_in[5];
    p.apw2 = (const float*)d_in[6];  p.apb2 = (const float*)d_in[7];
    p.anw1 = (const float*)d_in[8];  p.anb1 = (const float*)d_in[9];
    p.anw2 = (const float*)d_in[10]; p.anb2 = (const float*)d_in[11];
    p.arw  = (const float*)d_in[12]; p.arb  = (const float*)d_in[13];
    p.ciw  = (const float*)d_in[14]; p.cib  = (const float*)d_in[15];
    p.cpw1 = (const float*)d_in[16]; p.cpb1 = (const float*)d_in[17];
    p.cpw2 = (const float*)d_in[18]; p.cpb2 = (const float*)d_in[19];
    p.cnw1 = (const float*)d_in[20]; p.cnb1 = (const float*)d_in[21];
    p.cnw2 = (const float*)d_in[22]; p.cnb2 = (const float*)d_in[23];
    p.crw  = (const float*)d_in[24]; p.crb  = (const float*)d_in[25];
    p.K_i  = (const float*)d_in[26]; p.n_hill = (const float*)d_in[27];

    nnsys_kernel<<<1, 32>>>(p, (float*)d_out);
}